// round 2
// baseline (speedup 1.0000x reference)
#include <cuda_runtime.h>

#define Bb 64
#define Tt 512
#define Xx 8
#define Hh 128
#define H3 384

// Scratch for time-independent projections (device globals: no allocation).
__device__ float g_wi_c[(size_t)Bb * Tt * H3];        // [B,T,3H]   50.3 MB
__device__ float g_a_wi[(size_t)Bb * Tt * Hh];        // [B,T,H]    16.8 MB
__device__ float g_wi_w[(size_t)Bb * Tt * Xx * H3];   // [B,T,X,3H] 402 MB

// ---------------------------------------------------------------------------
// Generic C[M,N] = A[M,128] @ W[128,N] + bias[N], fp32, 64x64 tiles, 4x4 reg
// blocking, K=128 processed as two 64-chunks resident in static smem.
// grid = (N/64, M/64), block = 256.
// ---------------------------------------------------------------------------
__global__ __launch_bounds__(256) void gemm_bias_k128(
    const float* __restrict__ A, const float* __restrict__ W,
    const float* __restrict__ bias, float* __restrict__ C, int N)
{
    __shared__ float Ast[64][68];   // [k][m], padded
    __shared__ float Bs[64][68];    // [k][n], padded

    const int tx = threadIdx.x & 15;      // n-block
    const int ty = threadIdx.x >> 4;      // m-block
    const size_t m0 = (size_t)blockIdx.y * 64;
    const int n0 = blockIdx.x * 64;

    float acc[4][4];
#pragma unroll
    for (int i = 0; i < 4; i++)
#pragma unroll
        for (int j = 0; j < 4; j++) acc[i][j] = 0.f;

    for (int kc = 0; kc < 128; kc += 64) {
        // cooperative load: 64x64 A-chunk (transposed into Ast) + 64x64 W-chunk
#pragma unroll
        for (int i = 0; i < 4; i++) {
            int li = threadIdx.x + i * 256;
            int r  = li >> 4;              // 0..63
            int c4 = (li & 15) << 2;       // 0..60
            float4 av = *(const float4*)(A + (m0 + r) * 128 + kc + c4);
            Ast[c4 + 0][r] = av.x;
            Ast[c4 + 1][r] = av.y;
            Ast[c4 + 2][r] = av.z;
            Ast[c4 + 3][r] = av.w;
            float4 wv = *(const float4*)(W + (size_t)(kc + r) * N + n0 + c4);
            *(float4*)&Bs[r][c4] = wv;
        }
        __syncthreads();

#pragma unroll 16
        for (int k = 0; k < 64; k++) {
            float4 a  = *(const float4*)&Ast[k][ty << 2];
            float4 bv = *(const float4*)&Bs[k][tx << 2];
            acc[0][0] += a.x * bv.x; acc[0][1] += a.x * bv.y;
            acc[0][2] += a.x * bv.z; acc[0][3] += a.x * bv.w;
            acc[1][0] += a.y * bv.x; acc[1][1] += a.y * bv.y;
            acc[1][2] += a.y * bv.z; acc[1][3] += a.y * bv.w;
            acc[2][0] += a.z * bv.x; acc[2][1] += a.z * bv.y;
            acc[2][2] += a.z * bv.z; acc[2][3] += a.z * bv.w;
            acc[3][0] += a.w * bv.x; acc[3][1] += a.w * bv.y;
            acc[3][2] += a.w * bv.z; acc[3][3] += a.w * bv.w;
        }
        __syncthreads();
    }

#pragma unroll
    for (int i = 0; i < 4; i++) {
        size_t row = m0 + (ty << 2) + i;
#pragma unroll
        for (int j = 0; j < 4; j++) {
            int n = n0 + (tx << 2) + j;
            C[row * N + n] = acc[i][j] + bias[n];
        }
    }
}

// ---------------------------------------------------------------------------
// Fast activations (fp32, ~2-ulp via MUFU exp/rcp; well within 1e-3 budget)
// ---------------------------------------------------------------------------
__device__ __forceinline__ float sigf(float x)
{
    return __fdividef(1.f, 1.f + __expf(-x));
}
__device__ __forceinline__ float tanh_f(float x)
{
    // tanh(x) = 1 - 2/(e^{2x}+1); saturates correctly via expf over/underflow.
    return 1.f - __fdividef(2.f, __expf(2.f * x) + 1.f);
}

// ---------------------------------------------------------------------------
// Persistent scan: 1 CTA per batch, 384 threads. w_hh_w resident in SMEM.
// History is stored directly in the output arrays: hist slot s (s>=1) == row
// s-1 of hs/cs; slot 0 (zeros) is only "read" when fully masked (t=0, cnt=0),
// where the contribution is multiplied by exactly 0.
// ---------------------------------------------------------------------------
__global__ __launch_bounds__(384, 1) void lattice_scan(
    const float* __restrict__ w_hh_w, const float* __restrict__ w_hh_c,
    const float* __restrict__ a_hh, const int* __restrict__ skip_src,
    const int* __restrict__ skip_cnt, float* __restrict__ hs,
    float* __restrict__ cs)
{
    const int b = blockIdx.x;
    const int tid = threadIdx.x;

    extern __shared__ float sm[];
    float* sW   = sm;               // 128*384 = 49152 floats (w_hh_w resident)
    float* sH   = sW + Hh * H3;     // h_x  [8][128]
    float* sC   = sH + Xx * Hh;     // c_x  [8][128]
    float* sG   = sC + Xx * Hh;     // gw   [8][384]; reused for alpha [8][128]
    float* sC1s = sG + Xx * H3;     // c1_skip [8][128]
    float* sGc  = sC1s + Xx * Hh;   // gc [384]
    float* sH1  = sGc + H3;         // previous h1 [128]
    __shared__ int sSrc[Xx];
    __shared__ int sCnt;

    for (int i = tid; i < Hh * H3; i += 384) sW[i] = w_hh_w[i];
    if (tid < Hh) sH1[tid] = 0.f;

    const float* wiC = g_wi_c + (size_t)b * Tt * H3;
    const float* aWi = g_a_wi + (size_t)b * Tt * Hh;
    const float* wiW = g_wi_w + (size_t)b * Tt * Xx * H3;
    float* hsb = hs + (size_t)b * Tt * Hh;
    float* csb = cs + (size_t)b * Tt * Hh;

    __syncthreads();

    for (int t = 0; t < Tt; t++) {
        if (tid < Xx) sSrc[tid] = skip_src[((size_t)b * Tt + t) * Xx + tid];
        if (tid == Xx) sCnt = skip_cnt[(size_t)b * Tt + t];
        __syncthreads();

        // ---- gather h_x, c_x from history (output rows src) ----
        for (int i = tid; i < Xx * Hh; i += 384) {
            int x = i >> 7, k = i & 127;
            int s = sSrc[x];
            sH[i] = hsb[(size_t)s * Hh + k];
            sC[i] = csb[(size_t)s * Hh + k];
        }

        // ---- gc = h0 @ w_hh_c + wi_c   (GEMV, col = tid, weights from L2) --
        {
            float a0 = 0.f, a1 = 0.f, a2 = 0.f, a3 = 0.f;
#pragma unroll 8
            for (int k = 0; k < Hh; k += 4) {
                a0 += sH1[k + 0] * w_hh_c[(size_t)(k + 0) * H3 + tid];
                a1 += sH1[k + 1] * w_hh_c[(size_t)(k + 1) * H3 + tid];
                a2 += sH1[k + 2] * w_hh_c[(size_t)(k + 2) * H3 + tid];
                a3 += sH1[k + 3] * w_hh_c[(size_t)(k + 3) * H3 + tid];
            }
            sGc[tid] = (a0 + a1) + (a2 + a3) + wiC[(size_t)t * H3 + tid];
        }
        __syncthreads();

        // ---- gw = h_x @ w_hh_w + wi_w   ([8,128]@[128,384], smem weights) --
        {
            float acc[Xx];
#pragma unroll
            for (int x = 0; x < Xx; x++)
                acc[x] = wiW[((size_t)t * Xx + x) * H3 + tid];
#pragma unroll 4
            for (int k = 0; k < Hh; k += 4) {
                float w0 = sW[(k + 0) * H3 + tid];
                float w1 = sW[(k + 1) * H3 + tid];
                float w2 = sW[(k + 2) * H3 + tid];
                float w3 = sW[(k + 3) * H3 + tid];
#pragma unroll
                for (int x = 0; x < Xx; x++) {
                    float4 h4 = *(const float4*)&sH[x * Hh + k];
                    acc[x] += h4.x * w0 + h4.y * w1 + h4.z * w2 + h4.w * w3;
                }
            }
#pragma unroll
            for (int x = 0; x < Xx; x++) sG[x * H3 + tid] = acc[x];
        }
        __syncthreads();

        // ---- c1_skip = sig(f)*c_x + sig(i)*tanh(g) ----
        for (int i = tid; i < Xx * Hh; i += 384) {
            int x = i >> 7, h = i & 127;
            const float* g = sG + x * H3;
            sC1s[i] = sigf(g[h]) * sC[i] + sigf(g[Hh + h]) * tanh_f(g[2 * Hh + h]);
        }
        __syncthreads();

        // ---- alpha = sig(a_wi + c1_skip @ a_hh)  (256 threads, x split 2) --
        if (tid < 256) {
            int h = tid & 127;
            int x0 = (tid >> 7) << 2;    // 0 or 4
            float b0 = aWi[(size_t)t * Hh + h];
            float ac0 = b0, ac1 = b0, ac2 = b0, ac3 = b0;
#pragma unroll 8
            for (int k = 0; k < Hh; k++) {
                float av = a_hh[(size_t)k * Hh + h];
                ac0 += sC1s[(x0 + 0) * Hh + k] * av;
                ac1 += sC1s[(x0 + 1) * Hh + k] * av;
                ac2 += sC1s[(x0 + 2) * Hh + k] * av;
                ac3 += sC1s[(x0 + 3) * Hh + k] * av;
            }
            sG[(x0 + 0) * Hh + h] = sigf(ac0);
            sG[(x0 + 1) * Hh + h] = sigf(ac1);
            sG[(x0 + 2) * Hh + h] = sigf(ac2);
            sG[(x0 + 3) * Hh + h] = sigf(ac3);
        }
        __syncthreads();

        // ---- softmax-merge + output gate ----
        if (tid < Hh) {
            int h = tid;
            float i_g = sigf(sGc[h]);
            float o_g = sigf(sGc[Hh + h]);
            float g_g = tanh_f(sGc[2 * Hh + h]);
            float e0 = __expf(i_g);
            float num = g_g * e0;
            float den = e0;
            int cnt = sCnt;
#pragma unroll
            for (int x = 0; x < Xx; x++) {
                float e = (x < cnt) ? __expf(sG[x * Hh + h]) : 0.f;
                num += sC1s[x * Hh + h] * e;
                den += e;
            }
            float c1 = __fdividef(num, den);
            float h1 = o_g * tanh_f(c1);
            sH1[h] = h1;
            hsb[(size_t)t * Hh + h] = h1;
            csb[(size_t)t * Hh + h] = c1;
        }
        __syncthreads();
    }
}

// ---------------------------------------------------------------------------
extern "C" void kernel_launch(void* const* d_in, const int* in_sizes, int n_in,
                              void* d_out, int out_size)
{
    const float *inp, *skipw, *w_ih_c, *w_hh_c, *bias_c, *a_ih, *a_hh, *a_bias,
                *w_ih_w, *w_hh_w, *bias_w;
    const int *ssrc, *scnt;

    if (n_in >= 14 && in_sizes[2] == Bb) {
        // setup_inputs dict order: inp, skip_words, seq_len, skip_sources,
        // skip_count, w_ih_c, w_hh_c, bias_c, a_ih, a_hh, a_bias,
        // w_ih_w, w_hh_w, bias_w
        inp    = (const float*)d_in[0];
        skipw  = (const float*)d_in[1];
        ssrc   = (const int*)d_in[3];
        scnt   = (const int*)d_in[4];
        w_ih_c = (const float*)d_in[5];
        w_hh_c = (const float*)d_in[6];
        bias_c = (const float*)d_in[7];
        a_ih   = (const float*)d_in[8];
        a_hh   = (const float*)d_in[9];
        a_bias = (const float*)d_in[10];
        w_ih_w = (const float*)d_in[11];
        w_hh_w = (const float*)d_in[12];
        bias_w = (const float*)d_in[13];
    } else {
        // reference() signature order
        inp    = (const float*)d_in[0];
        skipw  = (const float*)d_in[1];
        w_ih_c = (const float*)d_in[2];
        w_hh_c = (const float*)d_in[3];
        bias_c = (const float*)d_in[4];
        a_ih   = (const float*)d_in[5];
        a_hh   = (const float*)d_in[6];
        a_bias = (const float*)d_in[7];
        w_ih_w = (const float*)d_in[8];
        w_hh_w = (const float*)d_in[9];
        bias_w = (const float*)d_in[10];
        ssrc   = (const int*)d_in[12];
        scnt   = (const int*)d_in[13];
    }

    float *pWiC, *pAWi, *pWiW;
    cudaGetSymbolAddress((void**)&pWiC, g_wi_c);
    cudaGetSymbolAddress((void**)&pAWi, g_a_wi);
    cudaGetSymbolAddress((void**)&pWiW, g_wi_w);

    dim3 blk(256);
    // wi_c_all = inp @ w_ih_c + bias_c           [32768, 384]
    gemm_bias_k128<<<dim3(6, (Bb * Tt) / 64), blk>>>(inp, w_ih_c, bias_c, pWiC, H3);
    // a_wi_all = inp @ a_ih + a_bias             [32768, 128]
    gemm_bias_k128<<<dim3(2, (Bb * Tt) / 64), blk>>>(inp, a_ih, a_bias, pAWi, Hh);
    // wi_w_all = skip_words @ w_ih_w + bias_w    [262144, 384]
    gemm_bias_k128<<<dim3(6, (Bb * Tt * Xx) / 64), blk>>>(skipw, w_ih_w, bias_w, pWiW, H3);

    const int SMEM_BYTES = (Hh * H3 + 3 * Xx * Hh + Xx * H3 + H3 + Hh) * 4; // 223232
    cudaFuncSetAttribute(lattice_scan,
                         cudaFuncAttributeMaxDynamicSharedMemorySize, SMEM_BYTES);

    float* hs = (float*)d_out;
    float* cs = hs + (size_t)Bb * Tt * Hh;
    lattice_scan<<<Bb, 384, SMEM_BYTES>>>(w_hh_w, w_hh_c, a_hh, ssrc, scnt, hs, cs);
}

// round 3
// speedup vs baseline: 1.3498x; 1.3498x over previous
#include <cuda_runtime.h>

#define Bb 64
#define Tt 512
#define Xx 8
#define Hh 128
#define H3 384
#define HALF 64          // h per CTA in the 2-CTA cluster split
#define C192 192         // local gate columns per CTA (3 gates * 64)

// Scratch for time-independent projections (device globals: no allocation).
__device__ float g_wi_c[(size_t)Bb * Tt * H3];        // [B,T,3H]
__device__ float g_a_wi[(size_t)Bb * Tt * Hh];        // [B,T,H]
__device__ float g_wi_w[(size_t)Bb * Tt * Xx * H3];   // [B,T,X,3H]

// ---------------------------------------------------------------------------
// C[M,N] = A[M,128] @ W[128,N] + bias[N], fp32, 64x64 tiles, 4x4 reg blocking.
// ---------------------------------------------------------------------------
__global__ __launch_bounds__(256) void gemm_bias_k128(
    const float* __restrict__ A, const float* __restrict__ W,
    const float* __restrict__ bias, float* __restrict__ C, int N)
{
    __shared__ float Ast[64][68];
    __shared__ float Bs[64][68];

    const int tx = threadIdx.x & 15;
    const int ty = threadIdx.x >> 4;
    const size_t m0 = (size_t)blockIdx.y * 64;
    const int n0 = blockIdx.x * 64;

    float acc[4][4];
#pragma unroll
    for (int i = 0; i < 4; i++)
#pragma unroll
        for (int j = 0; j < 4; j++) acc[i][j] = 0.f;

    for (int kc = 0; kc < 128; kc += 64) {
#pragma unroll
        for (int i = 0; i < 4; i++) {
            int li = threadIdx.x + i * 256;
            int r  = li >> 4;
            int c4 = (li & 15) << 2;
            float4 av = *(const float4*)(A + (m0 + r) * 128 + kc + c4);
            Ast[c4 + 0][r] = av.x;
            Ast[c4 + 1][r] = av.y;
            Ast[c4 + 2][r] = av.z;
            Ast[c4 + 3][r] = av.w;
            float4 wv = *(const float4*)(W + (size_t)(kc + r) * N + n0 + c4);
            *(float4*)&Bs[r][c4] = wv;
        }
        __syncthreads();

#pragma unroll 16
        for (int k = 0; k < 64; k++) {
            float4 a  = *(const float4*)&Ast[k][ty << 2];
            float4 bv = *(const float4*)&Bs[k][tx << 2];
            acc[0][0] += a.x * bv.x; acc[0][1] += a.x * bv.y;
            acc[0][2] += a.x * bv.z; acc[0][3] += a.x * bv.w;
            acc[1][0] += a.y * bv.x; acc[1][1] += a.y * bv.y;
            acc[1][2] += a.y * bv.z; acc[1][3] += a.y * bv.w;
            acc[2][0] += a.z * bv.x; acc[2][1] += a.z * bv.y;
            acc[2][2] += a.z * bv.z; acc[2][3] += a.z * bv.w;
            acc[3][0] += a.w * bv.x; acc[3][1] += a.w * bv.y;
            acc[3][2] += a.w * bv.z; acc[3][3] += a.w * bv.w;
        }
        __syncthreads();
    }

#pragma unroll
    for (int i = 0; i < 4; i++) {
        size_t row = m0 + (ty << 2) + i;
#pragma unroll
        for (int j = 0; j < 4; j++) {
            int n = n0 + (tx << 2) + j;
            C[row * N + n] = acc[i][j] + bias[n];
        }
    }
}

// ---------------------------------------------------------------------------
__device__ __forceinline__ float sigf(float x)
{
    return __fdividef(1.f, 1.f + __expf(-x));
}
__device__ __forceinline__ float tanh_f(float x)
{
    return 1.f - __fdividef(2.f, __expf(2.f * x) + 1.f);
}
__device__ __forceinline__ unsigned smem_u32(const void* p)
{
    unsigned a;
    asm("{ .reg .u64 t; cvta.to.shared.u64 t, %1; cvt.u32.u64 %0, t; }"
        : "=r"(a) : "l"(p));
    return a;
}
__device__ __forceinline__ unsigned mapa_u32(unsigned addr, unsigned rank)
{
    unsigned r;
    asm("mapa.shared::cluster.u32 %0, %1, %2;" : "=r"(r) : "r"(addr), "r"(rank));
    return r;
}
__device__ __forceinline__ void st_cluster_f32(unsigned addr, float v)
{
    asm volatile("st.shared::cluster.f32 [%0], %1;" :: "r"(addr), "f"(v) : "memory");
}
__device__ __forceinline__ void cluster_bar()
{
    asm volatile("barrier.cluster.arrive.aligned;" ::: "memory");
    asm volatile("barrier.cluster.wait.aligned;" ::: "memory");
}

// Dynamic smem layout (floats)
#define OFF_WW 0                      // [128][192] w_hh_w local cols  (24576)
#define OFF_AH 24576                  // [128][64]  a_hh local cols    (8192)
#define OFF_HX 32768                  // [8][128]   h_x full           (1024)
#define OFF_CX 33792                  // [8][64]    c_x half           (512)
#define OFF_GW 34304                  // [8][192]   gw local           (1536)
#define OFF_C1 35840                  // [8][128]   c1_skip full       (1024)
#define OFF_AL 36864                  // [8][64]    alpha local        (512)
#define OFF_GC 37376                  // [2][192]   gc partials        (384)
#define OFF_HP 37760                  // [128]      h_prev full        (128)
#define SMEM_FLOATS 37888

// ---------------------------------------------------------------------------
// Cluster-of-2 scan: 2 CTAs per batch, split by hidden index h.
// CTA rank r owns h in [r*64, r*64+64) for c1_skip/alpha/merge/outputs, and
// the 192 gate columns {g*128 + r*64 + j}. Exchanges c1_skip half + h1 half
// via DSMEM each step; barrier.cluster release/acquire also publishes the
// global h/c history rows for next step's gathers.
// ---------------------------------------------------------------------------
__global__ void __cluster_dims__(2, 1, 1) __launch_bounds__(384, 1)
lattice_scan(const float* __restrict__ w_hh_w, const float* __restrict__ w_hh_c,
             const float* __restrict__ a_hh, const int* __restrict__ skip_src,
             const int* __restrict__ skip_cnt, float* __restrict__ hs,
             float* __restrict__ cs)
{
    const int b   = blockIdx.x >> 1;
    const int tid = threadIdx.x;
    unsigned rank;
    asm("mov.u32 %0, %%cluster_ctarank;" : "=r"(rank));
    const int hBase = (int)rank * HALF;
    const unsigned peer = 1u - rank;

    extern __shared__ float sm[];
    float* sWw = sm + OFF_WW;
    float* sAh = sm + OFF_AH;
    float* sHx = sm + OFF_HX;
    float* sCx = sm + OFF_CX;
    float* sGw = sm + OFF_GW;
    float* sC1 = sm + OFF_C1;
    float* sAl = sm + OFF_AL;
    float* sGc = sm + OFF_GC;
    float* sHp = sm + OFF_HP;
    __shared__ int sSrcB[2][Xx];
    __shared__ int sCntB[2];

    const unsigned c1_peer = mapa_u32(smem_u32(sC1), peer);
    const unsigned hp_peer = mapa_u32(smem_u32(sHp), peer);

    // ---- one-time loads: local weight slices into smem ----
    for (int i = tid; i < 128 * C192; i += 384) {
        int k = i / C192, c = i - k * C192;
        int gcol = ((c >> 6) << 7) + hBase + (c & 63);
        sWw[i] = w_hh_w[(size_t)k * H3 + gcol];
    }
    for (int i = tid; i < 128 * HALF; i += 384) {
        int k = i >> 6, j = i & 63;
        sAh[i] = a_hh[(size_t)k * Hh + hBase + j];
    }
    if (tid < Hh) sHp[tid] = 0.f;
    if (tid < Xx) sSrcB[0][tid] = skip_src[(size_t)b * Tt * Xx + tid];
    if (tid == Xx) sCntB[0] = skip_cnt[(size_t)b * Tt];

    const float* wiC = g_wi_c + (size_t)b * Tt * H3;
    const float* aWi = g_a_wi + (size_t)b * Tt * Hh;
    const float* wiW = g_wi_w + (size_t)b * Tt * Xx * H3;
    float* hsb = hs + (size_t)b * Tt * Hh;
    float* csb = cs + (size_t)b * Tt * Hh;

    // gw thread mapping (fixed per thread)
    const int xh  = (tid >= C192) ? 1 : 0;      // x group: 0-3 or 4-7
    const int cg  = tid - xh * C192;            // local col 0..191
    const int gcw = ((cg >> 6) << 7) + hBase + (cg & 63);  // global gate col

    __syncthreads();

    for (int t = 0; t < Tt; t++) {
        const int buf = t & 1;

        // ---- P0: prefetch wiW into regs; prefetch next src/cnt; gather; gc --
        float rW0, rW1, rW2, rW3;
        {
            const float* wp = wiW + ((size_t)t * Xx + xh * 4) * H3 + gcw;
            rW0 = wp[0];
            rW1 = wp[H3];
            rW2 = wp[2 * H3];
            rW3 = wp[3 * H3];
        }
        {
            int tn = (t + 1 < Tt) ? t + 1 : t;
            if (tid < Xx)
                sSrcB[buf ^ 1][tid] = skip_src[((size_t)b * Tt + tn) * Xx + tid];
            else if (tid == Xx)
                sCntB[buf ^ 1] = skip_cnt[(size_t)b * Tt + tn];
        }
        {
            const int* srcC = sSrcB[buf];
            for (int i = tid; i < Xx * Hh; i += 384) {
                int x = i >> 7, k = i & 127;
                sHx[i] = hsb[(size_t)srcC[x] * Hh + k];
            }
            for (int i = tid; i < Xx * HALF; i += 384) {
                int x = i >> 6, j = i & 63;
                sCx[i] = csb[(size_t)srcC[x] * Hh + hBase + j];
            }
        }
        {   // gc partials: 192 cols x 2 k-halves
            int c  = (tid < C192) ? tid : tid - C192;
            int kh = (tid < C192) ? 0 : 1;
            int gcol = ((c >> 6) << 7) + hBase + (c & 63);
            const float* wc = w_hh_c + (size_t)(kh * 64) * H3 + gcol;
            const float* hp = sHp + kh * 64;
            float p0 = 0.f, p1 = 0.f, p2 = 0.f, p3 = 0.f;
#pragma unroll 4
            for (int k = 0; k < 64; k += 4) {
                p0 += hp[k + 0] * wc[(size_t)(k + 0) * H3];
                p1 += hp[k + 1] * wc[(size_t)(k + 1) * H3];
                p2 += hp[k + 2] * wc[(size_t)(k + 2) * H3];
                p3 += hp[k + 3] * wc[(size_t)(k + 3) * H3];
            }
            float r = (p0 + p1) + (p2 + p3);
            if (kh == 0) r += wiC[(size_t)t * H3 + gcol];
            sGc[kh * C192 + c] = r;
        }
        __syncthreads();

        // ---- P1: gw = h_x @ w_hh_w(local cols) + wiW  (4 accs/thread) ------
        {
            float a0 = rW0, a1 = rW1, a2 = rW2, a3 = rW3;
            const float* h0p = sHx + (xh * 4 + 0) * Hh;
            const float* h1p = sHx + (xh * 4 + 1) * Hh;
            const float* h2p = sHx + (xh * 4 + 2) * Hh;
            const float* h3p = sHx + (xh * 4 + 3) * Hh;
#pragma unroll 4
            for (int k = 0; k < 128; k += 4) {
                float w0 = sWw[(k + 0) * C192 + cg];
                float w1 = sWw[(k + 1) * C192 + cg];
                float w2 = sWw[(k + 2) * C192 + cg];
                float w3 = sWw[(k + 3) * C192 + cg];
                float4 v0 = *(const float4*)(h0p + k);
                float4 v1 = *(const float4*)(h1p + k);
                float4 v2 = *(const float4*)(h2p + k);
                float4 v3 = *(const float4*)(h3p + k);
                a0 += v0.x * w0 + v0.y * w1 + v0.z * w2 + v0.w * w3;
                a1 += v1.x * w0 + v1.y * w1 + v1.z * w2 + v1.w * w3;
                a2 += v2.x * w0 + v2.y * w1 + v2.z * w2 + v2.w * w3;
                a3 += v3.x * w0 + v3.y * w1 + v3.z * w2 + v3.w * w3;
            }
            sGw[(xh * 4 + 0) * C192 + cg] = a0;
            sGw[(xh * 4 + 1) * C192 + cg] = a1;
            sGw[(xh * 4 + 2) * C192 + cg] = a2;
            sGw[(xh * 4 + 3) * C192 + cg] = a3;
        }
        __syncthreads();

        // ---- P2: c1_skip (local half) + DSMEM exchange to peer --------------
        for (int i = tid; i < Xx * HALF; i += 384) {
            int x = i >> 6, j = i & 63;
            float f  = sGw[x * C192 + j];
            float iv = sGw[x * C192 + 64 + j];
            float g  = sGw[x * C192 + 128 + j];
            float v  = sigf(f) * sCx[x * HALF + j] + sigf(iv) * tanh_f(g);
            int off = x * Hh + hBase + j;
            sC1[off] = v;
            st_cluster_f32(c1_peer + (unsigned)off * 4u, v);
        }
        cluster_bar();

        // ---- P3: alpha = sig(a_wi + c1_skip_full @ a_hh(local cols)) -------
        if (tid < 256) {
            int j = tid & 63, xq = tid >> 6;
            int x0 = 2 * xq, x1 = 2 * xq + 1;
            float base = aWi[(size_t)t * Hh + hBase + j];
            float acc0 = base, acc1 = base;
#pragma unroll 4
            for (int k = 0; k < 128; k += 4) {
                float q0 = sAh[(k + 0) * HALF + j];
                float q1 = sAh[(k + 1) * HALF + j];
                float q2 = sAh[(k + 2) * HALF + j];
                float q3 = sAh[(k + 3) * HALF + j];
                float4 cA = *(const float4*)&sC1[x0 * Hh + k];
                float4 cB = *(const float4*)&sC1[x1 * Hh + k];
                acc0 += cA.x * q0 + cA.y * q1 + cA.z * q2 + cA.w * q3;
                acc1 += cB.x * q0 + cB.y * q1 + cB.z * q2 + cB.w * q3;
            }
            sAl[x0 * HALF + j] = sigf(acc0);
            sAl[x1 * HALF + j] = sigf(acc1);
        }
        __syncthreads();

        // ---- P4: softmax-merge, outputs, h1 exchange -----------------------
        if (tid < HALF) {
            int j = tid;
            float ig = sigf(sGc[j] + sGc[C192 + j]);
            float og = sigf(sGc[64 + j] + sGc[C192 + 64 + j]);
            float gg = tanh_f(sGc[128 + j] + sGc[C192 + 128 + j]);
            float e0 = __expf(ig);
            float num = gg * e0, den = e0;
            int cnt = sCntB[buf];
#pragma unroll
            for (int x = 0; x < Xx; x++) {
                float e = (x < cnt) ? __expf(sAl[x * HALF + j]) : 0.f;
                num += sC1[x * Hh + hBase + j] * e;
                den += e;
            }
            float c1v = __fdividef(num, den);
            float h1v = og * tanh_f(c1v);
            hsb[(size_t)t * Hh + hBase + j] = h1v;
            csb[(size_t)t * Hh + hBase + j] = c1v;
            sHp[hBase + j] = h1v;
            st_cluster_f32(hp_peer + (unsigned)(hBase + j) * 4u, h1v);
        }
        cluster_bar();   // publishes global h/c rows + h1/c1 exchanges
    }
}

// ---------------------------------------------------------------------------
extern "C" void kernel_launch(void* const* d_in, const int* in_sizes, int n_in,
                              void* d_out, int out_size)
{
    const float *inp, *skipw, *w_ih_c, *w_hh_c, *bias_c, *a_ih, *a_hh, *a_bias,
                *w_ih_w, *w_hh_w, *bias_w;
    const int *ssrc, *scnt;

    if (n_in >= 14 && in_sizes[2] == Bb) {
        inp    = (const float*)d_in[0];
        skipw  = (const float*)d_in[1];
        ssrc   = (const int*)d_in[3];
        scnt   = (const int*)d_in[4];
        w_ih_c = (const float*)d_in[5];
        w_hh_c = (const float*)d_in[6];
        bias_c = (const float*)d_in[7];
        a_ih   = (const float*)d_in[8];
        a_hh   = (const float*)d_in[9];
        a_bias = (const float*)d_in[10];
        w_ih_w = (const float*)d_in[11];
        w_hh_w = (const float*)d_in[12];
        bias_w = (const float*)d_in[13];
    } else {
        inp    = (const float*)d_in[0];
        skipw  = (const float*)d_in[1];
        w_ih_c = (const float*)d_in[2];
        w_hh_c = (const float*)d_in[3];
        bias_c = (const float*)d_in[4];
        a_ih   = (const float*)d_in[5];
        a_hh   = (const float*)d_in[6];
        a_bias = (const float*)d_in[7];
        w_ih_w = (const float*)d_in[8];
        w_hh_w = (const float*)d_in[9];
        bias_w = (const float*)d_in[10];
        ssrc   = (const int*)d_in[12];
        scnt   = (const int*)d_in[13];
    }

    float *pWiC, *pAWi, *pWiW;
    cudaGetSymbolAddress((void**)&pWiC, g_wi_c);
    cudaGetSymbolAddress((void**)&pAWi, g_a_wi);
    cudaGetSymbolAddress((void**)&pWiW, g_wi_w);

    dim3 blk(256);
    gemm_bias_k128<<<dim3(6, (Bb * Tt) / 64), blk>>>(inp, w_ih_c, bias_c, pWiC, H3);
    gemm_bias_k128<<<dim3(2, (Bb * Tt) / 64), blk>>>(inp, a_ih, a_bias, pAWi, Hh);
    gemm_bias_k128<<<dim3(6, (Bb * Tt * Xx) / 64), blk>>>(skipw, w_ih_w, bias_w, pWiW, H3);

    const int SMEM_BYTES = SMEM_FLOATS * 4;   // 151552
    cudaFuncSetAttribute(lattice_scan,
                         cudaFuncAttributeMaxDynamicSharedMemorySize, SMEM_BYTES);

    float* hs = (float*)d_out;
    float* cs = hs + (size_t)Bb * Tt * Hh;
    lattice_scan<<<Bb * 2, 384, SMEM_BYTES>>>(w_hh_w, w_hh_c, a_hh, ssrc, scnt,
                                              hs, cs);
}

// round 4
// speedup vs baseline: 1.6337x; 1.2103x over previous
#include <cuda_runtime.h>

#define Bb 64
#define Tt 512
#define Xx 8
#define Hh 128
#define H3 384
#define HALF 64
#define C192 192

typedef unsigned long long u64t;

// Scratch for time-independent projections (device globals: no allocation).
__device__ float g_wi_c[(size_t)Bb * Tt * H3];
__device__ float g_a_wi[(size_t)Bb * Tt * Hh];
__device__ float g_wi_w[(size_t)Bb * Tt * Xx * H3];

// ---------------------------------------------------------------------------
// C[M,N] = A[M,128] @ W[128,N] + bias[N], fp32, 64x64 tiles, 4x4 reg blocking.
// ---------------------------------------------------------------------------
__global__ __launch_bounds__(256) void gemm_bias_k128(
    const float* __restrict__ A, const float* __restrict__ W,
    const float* __restrict__ bias, float* __restrict__ C, int N)
{
    __shared__ float Ast[64][68];
    __shared__ float Bs[64][68];

    const int tx = threadIdx.x & 15;
    const int ty = threadIdx.x >> 4;
    const size_t m0 = (size_t)blockIdx.y * 64;
    const int n0 = blockIdx.x * 64;

    float acc[4][4];
#pragma unroll
    for (int i = 0; i < 4; i++)
#pragma unroll
        for (int j = 0; j < 4; j++) acc[i][j] = 0.f;

    for (int kc = 0; kc < 128; kc += 64) {
#pragma unroll
        for (int i = 0; i < 4; i++) {
            int li = threadIdx.x + i * 256;
            int r  = li >> 4;
            int c4 = (li & 15) << 2;
            float4 av = *(const float4*)(A + (m0 + r) * 128 + kc + c4);
            Ast[c4 + 0][r] = av.x;
            Ast[c4 + 1][r] = av.y;
            Ast[c4 + 2][r] = av.z;
            Ast[c4 + 3][r] = av.w;
            float4 wv = *(const float4*)(W + (size_t)(kc + r) * N + n0 + c4);
            *(float4*)&Bs[r][c4] = wv;
        }
        __syncthreads();

#pragma unroll 16
        for (int k = 0; k < 64; k++) {
            float4 a  = *(const float4*)&Ast[k][ty << 2];
            float4 bv = *(const float4*)&Bs[k][tx << 2];
            acc[0][0] += a.x * bv.x; acc[0][1] += a.x * bv.y;
            acc[0][2] += a.x * bv.z; acc[0][3] += a.x * bv.w;
            acc[1][0] += a.y * bv.x; acc[1][1] += a.y * bv.y;
            acc[1][2] += a.y * bv.z; acc[1][3] += a.y * bv.w;
            acc[2][0] += a.z * bv.x; acc[2][1] += a.z * bv.y;
            acc[2][2] += a.z * bv.z; acc[2][3] += a.z * bv.w;
            acc[3][0] += a.w * bv.x; acc[3][1] += a.w * bv.y;
            acc[3][2] += a.w * bv.z; acc[3][3] += a.w * bv.w;
        }
        __syncthreads();
    }

#pragma unroll
    for (int i = 0; i < 4; i++) {
        size_t row = m0 + (ty << 2) + i;
#pragma unroll
        for (int j = 0; j < 4; j++) {
            int n = n0 + (tx << 2) + j;
            C[row * N + n] = acc[i][j] + bias[n];
        }
    }
}

// ---------------------------------------------------------------------------
// helpers
// ---------------------------------------------------------------------------
__device__ __forceinline__ float sigf(float x)
{
    return __fdividef(1.f, 1.f + __expf(-x));
}
__device__ __forceinline__ float tanh_f(float x)
{
    return 1.f - __fdividef(2.f, __expf(2.f * x) + 1.f);
}
__device__ __forceinline__ unsigned smem_u32(const void* p)
{
    unsigned a;
    asm("{ .reg .u64 t; cvta.to.shared.u64 t, %1; cvt.u32.u64 %0, t; }"
        : "=r"(a) : "l"(p));
    return a;
}
__device__ __forceinline__ unsigned mapa_u32(unsigned addr, unsigned rank)
{
    unsigned r;
    asm("mapa.shared::cluster.u32 %0, %1, %2;" : "=r"(r) : "r"(addr), "r"(rank));
    return r;
}
__device__ __forceinline__ void st_cluster_f32(unsigned addr, float v)
{
    asm volatile("st.shared::cluster.f32 [%0], %1;" :: "r"(addr), "f"(v) : "memory");
}
__device__ __forceinline__ void mbar_init(unsigned addr, unsigned cnt)
{
    asm volatile("mbarrier.init.shared.b64 [%0], %1;" :: "r"(addr), "r"(cnt) : "memory");
}
__device__ __forceinline__ void mbar_arrive_remote(unsigned remote_addr)
{
    asm volatile("mbarrier.arrive.release.cluster.shared::cluster.b64 _, [%0];"
                 :: "r"(remote_addr) : "memory");
}
__device__ __forceinline__ void mbar_wait(unsigned addr, unsigned parity)
{
    asm volatile(
        "{\n\t.reg .pred P;\n\t"
        "WL_%=:\n\t"
        "mbarrier.try_wait.parity.acquire.cluster.shared::cta.b64 P, [%0], %1, 0x989680;\n\t"
        "@P bra.uni WD_%=;\n\t"
        "bra.uni WL_%=;\n\t"
        "WD_%=:\n\t}"
        :: "r"(addr), "r"(parity) : "memory");
}
__device__ __forceinline__ void fma2(u64t& d, u64t a, u64t b)
{
    asm("fma.rn.f32x2 %0, %1, %2, %0;" : "+l"(d) : "l"(a), "l"(b));
}
__device__ __forceinline__ u64t pk2(float lo, float hi)
{
    u64t r;
    asm("mov.b64 %0, {%1, %2};" : "=l"(r) : "f"(lo), "f"(hi));
    return r;
}
__device__ __forceinline__ void upk2(u64t v, float& lo, float& hi)
{
    asm("mov.b64 {%0, %1}, %2;" : "=f"(lo), "=f"(hi) : "l"(v));
}
__device__ __forceinline__ void lds_v2u64(unsigned addr, u64t& a, u64t& b)
{
    asm("ld.shared.v2.u64 {%0, %1}, [%2];" : "=l"(a), "=l"(b) : "r"(addr));
}
__device__ __forceinline__ void cluster_bar()
{
    asm volatile("barrier.cluster.arrive.aligned;" ::: "memory");
    asm volatile("barrier.cluster.wait.aligned;" ::: "memory");
}

// Dynamic smem layout (float offsets)
#define OFF_AHT 0        // [64][128] a_hh rows hBase..hBase+63     (8192)
#define OFF_HX  8192     // [128][12] h_x transposed, stride 12     (1536)
#define OFF_CX  9728     // [8][64]   c_x local half                (512)
#define OFF_GWA 10240    // [8][192]  gw partial k0-63              (1536)
#define OFF_GWB 11776    // [8][192]  gw partial k64-127            (1536)
#define OFF_C1  13312    // [8][64]   c1_skip local half            (512)
#define OFF_C1T 13824    // [64][12]  c1_skip transposed            (768)
#define OFF_ALO 14592    // [8][64]   alpha partial own             (512)
#define OFF_ALR 15104    // [8][64]   alpha partial recv            (512)
#define OFF_GCO 15616    // [192]     gc partial own                (192)
#define OFF_GCR 15808    // [192]     gc partial recv               (192)
#define OFF_GCP 16000    // [4][384]  gc k-quarter partials         (1536)
#define OFF_HP  17536    // [64]      h1 local half                 (64)
#define OFF_MB  17600    // 2 x u64 mbarriers (X, Y)                (4)
#define OFF_SRC 17604    // int [2][8]                              (16)
#define OFF_CNT 17620    // int [2]                                 (2)
#define SMEM_FLOATS 17624

// ---------------------------------------------------------------------------
// Cluster-of-2 scan with partial-sum exchange + mbarrier handshakes.
// ---------------------------------------------------------------------------
__global__ void __cluster_dims__(2, 1, 1) __launch_bounds__(384, 1)
lattice_scan(const float* __restrict__ w_hh_w, const float* __restrict__ w_hh_c,
             const float* __restrict__ a_hh, const int* __restrict__ skip_src,
             const int* __restrict__ skip_cnt, float* __restrict__ hs,
             float* __restrict__ cs)
{
    const int b   = blockIdx.x >> 1;
    const int tid = threadIdx.x;
    unsigned rank;
    asm("mov.u32 %0, %%cluster_ctarank;" : "=r"(rank));
    const int hBase = (int)rank * HALF;
    const unsigned peer = 1u - rank;

    extern __shared__ float sm[];
    float* sAht = sm + OFF_AHT;
    float* sCx  = sm + OFF_CX;
    float* sGwA = sm + OFF_GWA;
    float* sGwB = sm + OFF_GWB;
    float* sC1  = sm + OFF_C1;
    float* sC1t = sm + OFF_C1T;
    float* sAlO = sm + OFF_ALO;
    float* sAlR = sm + OFF_ALR;
    float* sGcO = sm + OFF_GCO;
    float* sGcR = sm + OFF_GCR;
    float* sGcP = sm + OFF_GCP;
    float* sHp  = sm + OFF_HP;
    int*   sSrc = (int*)(sm + OFF_SRC);
    int*   sCnt = (int*)(sm + OFF_CNT);
    float* sHx  = sm + OFF_HX;

    const unsigned uHX  = smem_u32(sHx);
    const unsigned uC1T = smem_u32(sC1t);
    const unsigned uMBX = smem_u32(sm + OFF_MB);
    const unsigned uMBY = uMBX + 8;
    const unsigned mbx_peer = mapa_u32(uMBX, peer);
    const unsigned mby_peer = mapa_u32(uMBY, peer);
    const unsigned alr_peer = mapa_u32(smem_u32(sAlR), peer);
    const unsigned gcr_peer = mapa_u32(smem_u32(sGcR), peer);

    // ---- thread roles for P1 (gw) ----
    const int kh  = (tid >= C192) ? 1 : 0;       // k-half
    const int cg  = tid - kh * C192;             // local col 0..191
    const int gcw = ((cg >> 6) << 7) + hBase + (cg & 63);  // global gate col

    // ---- prologue ----
    if (tid == 0) { mbar_init(uMBX, 1); mbar_init(uMBY, 1); }
    for (int i = tid; i < 64 * Hh; i += 384) {
        int kl = i >> 7, jg = i & 127;
        sAht[i] = a_hh[(size_t)(hBase + kl) * Hh + jg];
    }
    float wreg[64];
#pragma unroll
    for (int k = 0; k < 64; k++)
        wreg[k] = w_hh_w[(size_t)(kh * 64 + k) * H3 + gcw];
    if (tid < C192) { sGcO[tid] = 0.f; sGcR[tid] = 0.f; }
    if (tid < Xx) sSrc[tid] = skip_src[(size_t)b * Tt * Xx + tid];
    if (tid == Xx) sCnt[0] = skip_cnt[(size_t)b * Tt];

    const float* wiC = g_wi_c + (size_t)b * Tt * H3;
    const float* aWi = g_a_wi + (size_t)b * Tt * Hh;
    const float* wiW = g_wi_w + (size_t)b * Tt * Xx * H3;
    float* hsb = hs + (size_t)b * Tt * Hh;
    float* csb = cs + (size_t)b * Tt * Hh;

    __syncthreads();
    cluster_bar();   // mbarrier init visible cluster-wide before any arrive

    for (int t = 0; t < Tt; t++) {
        // ---- pre-wait prefetches (independent of Y) ----
        u64t a01, a23, a45, a67;
        if (!kh) {
            const float* wp = wiW + (size_t)t * Xx * H3 + gcw;
            float w0 = wp[0],      w1 = wp[H3],     w2 = wp[2 * H3], w3 = wp[3 * H3];
            float w4 = wp[4 * H3], w5 = wp[5 * H3], w6 = wp[6 * H3], w7 = wp[7 * H3];
            a01 = pk2(w0, w1); a23 = pk2(w2, w3);
            a45 = pk2(w4, w5); a67 = pk2(w6, w7);
        } else {
            a01 = a23 = a45 = a67 = 0ull;
        }
        {
            int tn = (t + 1 < Tt) ? t + 1 : t;
            if (tid < Xx)
                sSrc[((t + 1) & 1) * Xx + tid] = skip_src[((size_t)b * Tt + tn) * Xx + tid];
            else if (tid == Xx)
                sCnt[(t + 1) & 1] = skip_cnt[(size_t)b * Tt + tn];
        }

        if (t) mbar_wait(uMBY, (t + 1) & 1);   // peer gc-partials + history rows

        // ---- P0: gather h_x (transposed) / c_x (local half); gc finalize ----
        {
            const int* srcC = sSrc + (t & 1) * Xx;
            int x0 = tid >> 7,        k0 = tid & 127;
            int x1 = (tid + 384) >> 7, k1 = (tid + 384) & 127;
            float h0 = hsb[(size_t)srcC[x0] * Hh + k0];
            float h1 = hsb[(size_t)srcC[x1] * Hh + k1];
            float h2 = 0.f; int x2 = 0, k2 = 0;
            if (tid < 256) {
                x2 = (tid + 768) >> 7; k2 = (tid + 768) & 127;
                h2 = hsb[(size_t)srcC[x2] * Hh + k2];
            }
            int cx0 = tid >> 6, cj0 = tid & 63;
            float c0 = csb[(size_t)srcC[cx0] * Hh + hBase + cj0];
            float c1l = 0.f; int cx1 = 0, cj1 = 0;
            if (tid < 128) {
                cx1 = (tid + 384) >> 6; cj1 = (tid + 384) & 63;
                c1l = csb[(size_t)srcC[cx1] * Hh + hBase + cj1];
            }
            sHx[k0 * 12 + x0] = h0;
            sHx[k1 * 12 + x1] = h1;
            if (tid < 256) sHx[k2 * 12 + x2] = h2;
            sCx[cx0 * HALF + cj0] = c0;
            if (tid < 128) sCx[cx1 * HALF + cj1] = c1l;
        }
        if (tid < C192) {
            int gcol = ((tid >> 6) << 7) + hBase + (tid & 63);
            sGcO[tid] = sGcO[tid] + sGcR[tid] + wiC[(size_t)t * H3 + gcol];
        }
        __syncthreads();   // S1

        // ---- P1: gw partials (f32x2, register weights, broadcast LDS) ------
        {
            const unsigned hxa = uHX + (unsigned)(kh * 64) * 48u;
#pragma unroll
            for (int k = 0; k < 64; k++) {
                u64t h01, h23, h45, h67;
                lds_v2u64(hxa + (unsigned)k * 48u, h01, h23);
                lds_v2u64(hxa + (unsigned)k * 48u + 16u, h45, h67);
                u64t wp = pk2(wreg[k], wreg[k]);
                fma2(a01, h01, wp);
                fma2(a23, h23, wp);
                fma2(a45, h45, wp);
                fma2(a67, h67, wp);
            }
            float* dst = kh ? sGwB : sGwA;
            float lo, hi;
            upk2(a01, lo, hi); dst[0 * C192 + cg] = lo; dst[1 * C192 + cg] = hi;
            upk2(a23, lo, hi); dst[2 * C192 + cg] = lo; dst[3 * C192 + cg] = hi;
            upk2(a45, lo, hi); dst[4 * C192 + cg] = lo; dst[5 * C192 + cg] = hi;
            upk2(a67, lo, hi); dst[6 * C192 + cg] = lo; dst[7 * C192 + cg] = hi;
        }
        __syncthreads();   // S2

        // ---- P2: c1_skip local half (both layouts) -------------------------
        {
            int i = tid;
            {
                int x = i >> 6, jl = i & 63;
                float f  = sGwA[x * C192 + jl]       + sGwB[x * C192 + jl];
                float iv = sGwA[x * C192 + 64 + jl]  + sGwB[x * C192 + 64 + jl];
                float g  = sGwA[x * C192 + 128 + jl] + sGwB[x * C192 + 128 + jl];
                float v  = sigf(f) * sCx[x * HALF + jl] + sigf(iv) * tanh_f(g);
                sC1[x * HALF + jl] = v;
                sC1t[jl * 12 + x]  = v;
            }
            if (tid < 128) {
                i = tid + 384;
                int x = i >> 6, jl = i & 63;
                float f  = sGwA[x * C192 + jl]       + sGwB[x * C192 + jl];
                float iv = sGwA[x * C192 + 64 + jl]  + sGwB[x * C192 + 64 + jl];
                float g  = sGwA[x * C192 + 128 + jl] + sGwB[x * C192 + 128 + jl];
                float v  = sigf(f) * sCx[x * HALF + jl] + sigf(iv) * tanh_f(g);
                sC1[x * HALF + jl] = v;
                sC1t[jl * 12 + x]  = v;
            }
        }
        __syncthreads();   // S3

        // ---- P2b: alpha partial over local k-half; send peer's j-half ------
        if (tid < Hh) {
            const int jg = tid;
            u64t p01 = 0, p23 = 0, p45 = 0, p67 = 0;
#pragma unroll 8
            for (int kl = 0; kl < 64; kl++) {
                u64t c01, c23, c45, c67;
                lds_v2u64(uC1T + (unsigned)kl * 48u, c01, c23);
                lds_v2u64(uC1T + (unsigned)kl * 48u + 16u, c45, c67);
                float w = sAht[kl * Hh + jg];
                u64t wp = pk2(w, w);
                fma2(p01, c01, wp);
                fma2(p23, c23, wp);
                fma2(p45, c45, wp);
                fma2(p67, c67, wp);
            }
            float v[8];
            upk2(p01, v[0], v[1]);
            upk2(p23, v[2], v[3]);
            upk2(p45, v[4], v[5]);
            upk2(p67, v[6], v[7]);
            int jl = jg & 63;
            if ((jg >> 6) == (int)rank) {
#pragma unroll
                for (int x = 0; x < Xx; x++) sAlO[x * HALF + jl] = v[x];
            } else {
#pragma unroll
                for (int x = 0; x < Xx; x++)
                    st_cluster_f32(alr_peer + (unsigned)(x * HALF + jl) * 4u, v[x]);
            }
        }
        __syncthreads();   // S4
        if (tid == 0) mbar_arrive_remote(mbx_peer);
        mbar_wait(uMBX, t & 1);

        // ---- P4: merge + outputs (local j half) ----------------------------
        if (tid < HALF) {
            int j = tid;
            float ig = sigf(sGcO[j]);
            float og = sigf(sGcO[64 + j]);
            float gg = tanh_f(sGcO[128 + j]);
            float e0 = __expf(ig);
            float num = gg * e0, den = e0;
            float aw = aWi[(size_t)t * Hh + hBase + j];
            int cnt = sCnt[t & 1];
#pragma unroll
            for (int x = 0; x < Xx; x++) {
                float a = sigf(aw + sAlO[x * HALF + j] + sAlR[x * HALF + j]);
                float e = (x < cnt) ? __expf(a) : 0.f;
                num += sC1[x * HALF + j] * e;
                den += e;
            }
            float c1v = __fdividef(num, den);
            float h1v = og * tanh_f(c1v);
            hsb[(size_t)t * Hh + hBase + j] = h1v;
            csb[(size_t)t * Hh + hBase + j] = c1v;
            sHp[j] = h1v;
        }

        if (t + 1 < Tt) {
            __syncthreads();   // S5: sHp + global rows done
            // ---- gc partials for step t+1: local h1 half x w_hh_c ----------
            {
                int kq = tid / 96;
                int c4 = (tid - kq * 96) * 4;
                const float* wc = w_hh_c + (size_t)(hBase + kq * 16) * H3 + c4;
                float ax = 0.f, ay = 0.f, az = 0.f, aw2 = 0.f;
#pragma unroll
                for (int kk = 0; kk < 16; kk++) {
                    float h = sHp[kq * 16 + kk];
                    float4 w = *(const float4*)(wc + (size_t)kk * H3);
                    ax += h * w.x; ay += h * w.y; az += h * w.z; aw2 += h * w.w;
                }
                float4 r = make_float4(ax, ay, az, aw2);
                *(float4*)&sGcP[kq * H3 + c4] = r;
            }
            __syncthreads();   // S6
            {
                int col = tid;
                float s = sGcP[col] + sGcP[H3 + col] + sGcP[2 * H3 + col] +
                          sGcP[3 * H3 + col];
                int off = col & 127;
                int cgl = ((col >> 7) << 6) + (off & 63);
                if ((off >> 6) == (int)rank) sGcO[cgl] = s;
                else st_cluster_f32(gcr_peer + (unsigned)cgl * 4u, s);
            }
            __syncthreads();   // S7
            if (tid == 0) mbar_arrive_remote(mby_peer);
        }
    }

    cluster_bar();   // no CTA exits while peer DSMEM traffic may be in flight
}

// ---------------------------------------------------------------------------
extern "C" void kernel_launch(void* const* d_in, const int* in_sizes, int n_in,
                              void* d_out, int out_size)
{
    const float *inp, *skipw, *w_ih_c, *w_hh_c, *bias_c, *a_ih, *a_hh, *a_bias,
                *w_ih_w, *w_hh_w, *bias_w;
    const int *ssrc, *scnt;

    if (n_in >= 14 && in_sizes[2] == Bb) {
        inp    = (const float*)d_in[0];
        skipw  = (const float*)d_in[1];
        ssrc   = (const int*)d_in[3];
        scnt   = (const int*)d_in[4];
        w_ih_c = (const float*)d_in[5];
        w_hh_c = (const float*)d_in[6];
        bias_c = (const float*)d_in[7];
        a_ih   = (const float*)d_in[8];
        a_hh   = (const float*)d_in[9];
        a_bias = (const float*)d_in[10];
        w_ih_w = (const float*)d_in[11];
        w_hh_w = (const float*)d_in[12];
        bias_w = (const float*)d_in[13];
    } else {
        inp    = (const float*)d_in[0];
        skipw  = (const float*)d_in[1];
        w_ih_c = (const float*)d_in[2];
        w_hh_c = (const float*)d_in[3];
        bias_c = (const float*)d_in[4];
        a_ih   = (const float*)d_in[5];
        a_hh   = (const float*)d_in[6];
        a_bias = (const float*)d_in[7];
        w_ih_w = (const float*)d_in[8];
        w_hh_w = (const float*)d_in[9];
        bias_w = (const float*)d_in[10];
        ssrc   = (const int*)d_in[12];
        scnt   = (const int*)d_in[13];
    }

    float *pWiC, *pAWi, *pWiW;
    cudaGetSymbolAddress((void**)&pWiC, g_wi_c);
    cudaGetSymbolAddress((void**)&pAWi, g_a_wi);
    cudaGetSymbolAddress((void**)&pWiW, g_wi_w);

    dim3 blk(256);
    gemm_bias_k128<<<dim3(6, (Bb * Tt) / 64), blk>>>(inp, w_ih_c, bias_c, pWiC, H3);
    gemm_bias_k128<<<dim3(2, (Bb * Tt) / 64), blk>>>(inp, a_ih, a_bias, pAWi, Hh);
    gemm_bias_k128<<<dim3(6, (Bb * Tt * Xx) / 64), blk>>>(skipw, w_ih_w, bias_w, pWiW, H3);

    const int SMEM_BYTES = SMEM_FLOATS * 4;   // ~70.5 KB
    cudaFuncSetAttribute(lattice_scan,
                         cudaFuncAttributeMaxDynamicSharedMemorySize, SMEM_BYTES);

    float* hs = (float*)d_out;
    float* cs = hs + (size_t)Bb * Tt * Hh;
    lattice_scan<<<Bb * 2, 384, SMEM_BYTES>>>(w_hh_w, w_hh_c, a_hh, ssrc, scnt,
                                              hs, cs);
}